// round 5
// baseline (speedup 1.0000x reference)
#include <cuda_runtime.h>
#include <math.h>

#define BB   4
#define CIN  64
#define C2   340
#define HID  170
#define HH   256
#define WW   256
#define NPIX 65536   /* 256*256 */

// ---------------- scratch (device globals; no allocations) ----------------
__device__ float g_xd[BB * CIN * NPIX];          // DCT(x): 67 MB
__device__ float g_yq[BB * C2  * NPIX];          // quant * (W_in @ DCT(x)): 356 MB
__device__ float g_g [BB * HID * NPIX];          // gelu(x1)*x2: 178 MB
__device__ float g_Wt [64  * 384];               // W_in^T  [k][m], stride 384 (zero padded)
__device__ float g_Wot[170 * 64];                // W_out^T [k][m]

// ---------------- tiny transpose of the weight matrices ----------------
__global__ void k_transpose(const float* __restrict__ W_in,
                            const float* __restrict__ W_out) {
    int t = blockIdx.x * blockDim.x + threadIdx.x;
    if (t < C2 * CIN) {               // W_in [340][64] -> g_Wt [64][384]
        int m = t / CIN, k = t % CIN;
        g_Wt[k * 384 + m] = W_in[t];
    }
    if (t < 64 * HID) {               // W_out [64][170] -> g_Wot [170][64]
        int m = t / HID, k = t % HID;
        g_Wot[k * 64 + m] = W_out[t];
    }
}

// ---------------- K1: per-patch 2D DCT of x (64 channels) ----------------
// block: one (b, c, patch-row). xd = M @ X @ M^T per 8x8 patch.
__global__ __launch_bounds__(256) void k_dct(const float* __restrict__ x) {
    __shared__ float Ms[64];
    __shared__ float xs[8 * 256];
    int tid = threadIdx.x;
    if (tid < 64) {
        int i = tid >> 3, j = tid & 7;
        Ms[tid] = (i == 0) ? 0.35355339059327373f
                           : 0.5f * cospif((float)(i * (2 * j + 1)) * (1.0f / 16.0f));
    }
    int pr = blockIdx.x, c = blockIdx.y, b = blockIdx.z;
    const float* src = x + ((size_t)(b * CIN + c) * HH + pr * 8) * WW;
    for (int i = tid; i < 8 * 64; i += 256) {
        int r = i >> 6, q4 = i & 63;
        *(float4*)&xs[r * 256 + q4 * 4] = *(const float4*)(src + r * WW + q4 * 4);
    }
    __syncthreads();
    {   // stage A: column transform (M @ X), in place, thread owns a column
        int col = tid;
        float u[8];
        #pragma unroll
        for (int p = 0; p < 8; p++) u[p] = xs[p * 256 + col];
        #pragma unroll
        for (int i = 0; i < 8; i++) {
            float s = 0.f;
            #pragma unroll
            for (int p = 0; p < 8; p++) s += Ms[i * 8 + p] * u[p];
            xs[i * 256 + col] = s;
        }
    }
    __syncthreads();
    {   // stage B: row transform (T @ M^T), thread owns (row, patch-col), store direct
        float* dst = g_xd + ((size_t)(b * CIN + c) * HH + pr * 8) * WW;
        int row = tid >> 5, pc = tid & 31;
        float4 v0 = *(float4*)&xs[row * 256 + pc * 8];
        float4 v1 = *(float4*)&xs[row * 256 + pc * 8 + 4];
        float u[8] = {v0.x, v0.y, v0.z, v0.w, v1.x, v1.y, v1.z, v1.w};
        float y[8];
        #pragma unroll
        for (int j = 0; j < 8; j++) {
            float s = 0.f;
            #pragma unroll
            for (int q = 0; q < 8; q++) s += u[q] * Ms[j * 8 + q];
            y[j] = s;
        }
        *(float4*)(dst + row * 256 + pc * 8)     = make_float4(y[0], y[1], y[2], y[3]);
        *(float4*)(dst + row * 256 + pc * 8 + 4) = make_float4(y[4], y[5], y[6], y[7]);
    }
}

// ---------------- K2: yq = quant * (W_in @ xd)  (GEMM M=340,K=64,N=65536 per batch)
__global__ __launch_bounds__(256) void k_proj_in(const float* __restrict__ quant) {
    __shared__ float As[64][64];    // [k][m]
    __shared__ float Bs[64][128];   // [k][n]
    int n0 = blockIdx.x * 128;
    int m0 = blockIdx.y * 64;
    int b  = blockIdx.z;
    int tid = threadIdx.x;

    for (int i = tid; i < 64 * 16; i += 256) {      // A tile (pre-transposed, padded)
        int k = i >> 4, m4 = i & 15;
        *(float4*)&As[k][m4 * 4] = *(const float4*)(g_Wt + k * 384 + m0 + m4 * 4);
    }
    const float* Bbase = g_xd + (size_t)b * CIN * NPIX + n0;
    for (int i = tid; i < 64 * 32; i += 256) {      // B tile
        int k = i >> 5, n4 = i & 31;
        *(float4*)&Bs[k][n4 * 4] = *(const float4*)(Bbase + (size_t)k * NPIX + n4 * 4);
    }
    __syncthreads();

    int tmg = tid >> 5, tng = tid & 31;             // 8 m-groups x 32 n-groups
    float acc[8][4];
    #pragma unroll
    for (int m = 0; m < 8; m++) { acc[m][0] = acc[m][1] = acc[m][2] = acc[m][3] = 0.f; }

    #pragma unroll 8
    for (int k = 0; k < 64; k++) {
        float4 bv = *(float4*)&Bs[k][tng * 4];
        float4 a0 = *(float4*)&As[k][tmg * 8];
        float4 a1 = *(float4*)&As[k][tmg * 8 + 4];
        float a[8] = {a0.x, a0.y, a0.z, a0.w, a1.x, a1.y, a1.z, a1.w};
        #pragma unroll
        for (int m = 0; m < 8; m++) {
            acc[m][0] += a[m] * bv.x; acc[m][1] += a[m] * bv.y;
            acc[m][2] += a[m] * bv.z; acc[m][3] += a[m] * bv.w;
        }
    }

    int fi  = (n0 >> 8) & 7;          // all 128 pixels in the tile share h
    int fjb = (tng & 1) * 4;          // fj base for this thread's 4 pixels
    float* dstbase = g_yq + (size_t)b * C2 * NPIX + n0 + tng * 4;
    #pragma unroll
    for (int m = 0; m < 8; m++) {
        int cc = m0 + tmg * 8 + m;
        if (cc < C2) {
            float4 qv = *(const float4*)(quant + cc * 64 + fi * 8 + fjb);
            float4 o = make_float4(acc[m][0] * qv.x, acc[m][1] * qv.y,
                                   acc[m][2] * qv.z, acc[m][3] * qv.w);
            *(float4*)(dstbase + (size_t)cc * NPIX) = o;
        }
    }
}

// ---------------- K3: fused IDCT + depthwise 3x3 + GLU(gelu) -> g ----------------
// block: (y-tile of 32 rows, gate channel c, batch). Loads yq rows [y0-8, y0+40)
// (zero outside image), IDCT in smem, dw with zero padding; phase0 = x1 (gelu arg),
// phase1 = x2, writes g = gelu(x1) * x2.
__global__ __launch_bounds__(512) void k_fuse(const float* __restrict__ W_dw) {
    extern __shared__ float sm[];
    float* yA  = sm;               // 48 rows * 256
    float* dwA = sm + 48 * 256;    // 32 rows * 256
    __shared__ float Ms[64];
    int tid = threadIdx.x;
    if (tid < 64) {
        int i = tid >> 3, j = tid & 7;
        Ms[tid] = (i == 0) ? 0.35355339059327373f
                           : 0.5f * cospif((float)(i * (2 * j + 1)) * (1.0f / 16.0f));
    }
    int yt = blockIdx.x, c = blockIdx.y, b = blockIdx.z;
    int y0 = yt * 32;

    for (int phase = 0; phase < 2; phase++) {
        int ch = c + phase * HID;
        const float* src = g_yq + (size_t)(b * C2 + ch) * NPIX;
        for (int i = tid; i < 48 * 64; i += 512) {
            int r = i >> 6, q4 = i & 63;
            int gy = y0 - 8 + r;
            float4 v = make_float4(0.f, 0.f, 0.f, 0.f);
            if (gy >= 0 && gy < HH) v = *(const float4*)(src + gy * WW + q4 * 4);
            *(float4*)&yA[r * 256 + q4 * 4] = v;
        }
        __syncthreads();
        // IDCT stage 1: column transform (M^T @ Yq) per patch-row, in place
        for (int i = tid; i < 6 * 256; i += 512) {
            int prow = i >> 8, col = i & 255;
            float u[8];
            #pragma unroll
            for (int p = 0; p < 8; p++) u[p] = yA[(prow * 8 + p) * 256 + col];
            #pragma unroll
            for (int r = 0; r < 8; r++) {
                float s = 0.f;
                #pragma unroll
                for (int p = 0; p < 8; p++) s += Ms[p * 8 + r] * u[p];
                yA[(prow * 8 + r) * 256 + col] = s;
            }
        }
        __syncthreads();
        // IDCT stage 2: row transform (U @ M), thread owns (row, patch-col), in place
        for (int i = tid; i < 48 * 32; i += 512) {
            int row = i >> 5, pc = i & 31;
            float4 v0 = *(float4*)&yA[row * 256 + pc * 8];
            float4 v1 = *(float4*)&yA[row * 256 + pc * 8 + 4];
            float u[8] = {v0.x, v0.y, v0.z, v0.w, v1.x, v1.y, v1.z, v1.w};
            float yv[8];
            #pragma unroll
            for (int j = 0; j < 8; j++) {
                float s = 0.f;
                #pragma unroll
                for (int q = 0; q < 8; q++) s += u[q] * Ms[q * 8 + j];
                yv[j] = s;
            }
            *(float4*)&yA[row * 256 + pc * 8]     = make_float4(yv[0], yv[1], yv[2], yv[3]);
            *(float4*)&yA[row * 256 + pc * 8 + 4] = make_float4(yv[4], yv[5], yv[6], yv[7]);
        }
        __syncthreads();
        // depthwise 3x3 (zero padded)
        float w9[9];
        #pragma unroll
        for (int t = 0; t < 9; t++) w9[t] = __ldg(&W_dw[ch * 9 + t]);
        if (phase == 0) {
            for (int i = tid; i < 32 * 256; i += 512) {
                int r = i >> 8, w = i & 255;
                float s = 0.f;
                #pragma unroll
                for (int dy = -1; dy <= 1; dy++) {
                    #pragma unroll
                    for (int dx = -1; dx <= 1; dx++) {
                        int ww = w + dx;
                        float v = (ww >= 0 && ww < WW) ? yA[(r + 8 + dy) * 256 + ww] : 0.f;
                        s += v * w9[(dy + 1) * 3 + (dx + 1)];
                    }
                }
                dwA[i] = s;
            }
        } else {
            float* gdst = g_g + (size_t)(b * HID + c) * NPIX + (size_t)y0 * WW;
            for (int i = tid; i < 32 * 256; i += 512) {
                int r = i >> 8, w = i & 255;
                float s = 0.f;
                #pragma unroll
                for (int dy = -1; dy <= 1; dy++) {
                    #pragma unroll
                    for (int dx = -1; dx <= 1; dx++) {
                        int ww = w + dx;
                        float v = (ww >= 0 && ww < WW) ? yA[(r + 8 + dy) * 256 + ww] : 0.f;
                        s += v * w9[(dy + 1) * 3 + (dx + 1)];
                    }
                }
                float x1  = dwA[i];
                float gel = 0.5f * x1 * (1.f + erff(x1 * 0.70710678118654752f));
                gdst[i] = gel * s;
            }
        }
        __syncthreads();
    }
}

// ---------------- K4: out = W_out @ g  (GEMM M=64, K=170, N=65536 per batch)
__global__ __launch_bounds__(256) void k_proj_out(float* __restrict__ out) {
    __shared__ float As[34][64];
    __shared__ float Bs[34][128];
    int n0 = blockIdx.x * 128, b = blockIdx.y, tid = threadIdx.x;
    int tmg = tid >> 5, tng = tid & 31;
    float acc[8][4];
    #pragma unroll
    for (int m = 0; m < 8; m++) { acc[m][0] = acc[m][1] = acc[m][2] = acc[m][3] = 0.f; }

    for (int kk = 0; kk < HID; kk += 34) {
        for (int i = tid; i < 34 * 16; i += 256) {
            int k = i >> 4, m4 = i & 15;
            *(float4*)&As[k][m4 * 4] = *(const float4*)(g_Wot + (kk + k) * 64 + m4 * 4);
        }
        for (int i = tid; i < 34 * 32; i += 256) {
            int k = i >> 5, n4 = i & 31;
            *(float4*)&Bs[k][n4 * 4] =
                *(const float4*)(g_g + (size_t)(b * HID + kk + k) * NPIX + n0 + n4 * 4);
        }
        __syncthreads();
        #pragma unroll
        for (int k = 0; k < 34; k++) {
            float4 bv = *(float4*)&Bs[k][tng * 4];
            float4 a0 = *(float4*)&As[k][tmg * 8];
            float4 a1 = *(float4*)&As[k][tmg * 8 + 4];
            float a[8] = {a0.x, a0.y, a0.z, a0.w, a1.x, a1.y, a1.z, a1.w};
            #pragma unroll
            for (int m = 0; m < 8; m++) {
                acc[m][0] += a[m] * bv.x; acc[m][1] += a[m] * bv.y;
                acc[m][2] += a[m] * bv.z; acc[m][3] += a[m] * bv.w;
            }
        }
        __syncthreads();
    }
    #pragma unroll
    for (int m = 0; m < 8; m++) {
        *(float4*)(out + (size_t)(b * 64 + tmg * 8 + m) * NPIX + n0 + tng * 4) =
            make_float4(acc[m][0], acc[m][1], acc[m][2], acc[m][3]);
    }
}

// ---------------- launch ----------------
extern "C" void kernel_launch(void* const* d_in, const int* in_sizes, int n_in,
                              void* d_out, int out_size) {
    (void)in_sizes; (void)n_in; (void)out_size;
    const float* x     = (const float*)d_in[0];
    const float* W_in  = (const float*)d_in[1];
    const float* W_dw  = (const float*)d_in[2];
    const float* quant = (const float*)d_in[3];
    const float* W_out = (const float*)d_in[4];
    float* out = (float*)d_out;

    cudaFuncSetAttribute(k_fuse, cudaFuncAttributeMaxDynamicSharedMemorySize,
                         (48 + 32) * 256 * 4);

    k_transpose<<<85, 256>>>(W_in, W_out);
    k_dct<<<dim3(32, 64, 4), 256>>>(x);
    k_proj_in<<<dim3(512, 6, 4), 256>>>(quant);
    k_fuse<<<dim3(8, 170, 4), 512, (48 + 32) * 256 * 4>>>(W_dw);
    k_proj_out<<<dim3(512, 4), 256>>>(out);
}